// round 16
// baseline (speedup 1.0000x reference)
#include <cuda_runtime.h>
#include <math.h>

#define NN 10000
#define EORIG 50000
#define EDOUB 100000
#define BB 4
#define NT 40000
#define DD 64
#define KS_N 4000u
#define ES_E 40000u
#define SELB 157

// ------------------------- device scratch (zero-initialized at load) ------
__device__ float g_hidden[NT * DD];
__device__ float g_score[NT];
__device__ float g_feat[NT * 256];
__device__ float g_C[NT * 192];
__device__ float g_Wcat[3 * 256 * 192];
__device__ float g_qpart[DD];
__device__ float g_deg[NT];
__device__ float g_csum[192];
__device__ float g_updB[256 * 64];
__device__ float g_scoreB[256];
__device__ float g_partial[40];
__device__ float g_headsc[4];
__device__ int   g_ptr[NN + 1];
__device__ int   g_cur[NN];
__device__ int   g_cnt[NN];
__device__ int   g_adj[EDOUB];
__device__ int   g_wlist[NT];
__device__ int   g_dirty[NT];
__device__ int   g_dlist[512];
__device__ int   g_nd;
__device__ unsigned g_binsA[2048];
__device__ unsigned g_binsB[2048];
__device__ float g_pna;
__device__ float g_thr;
__device__ float g_T;
__device__ unsigned g_prefixC, g_kremC, g_prefixW, g_kremW;
__device__ int g_wl;
__device__ int g_ticket;
__device__ unsigned g_release;

// ------------------------- helpers -------------------------
__device__ __forceinline__ unsigned f2key(float f) {
    unsigned u = __float_as_uint(f);
    return (u & 0x80000000u) ? ~u : (u | 0x80000000u);
}
__device__ __forceinline__ float key2f(unsigned key) {
    unsigned u = (key & 0x80000000u) ? (key & 0x7FFFFFFFu) : ~key;
    return __uint_as_float(u);
}

__device__ __forceinline__ void warpHistAdd(unsigned* bins, unsigned bin, unsigned w, unsigned NB) {
    unsigned m = __match_any_sync(0xffffffffu, bin);
    int lane = threadIdx.x & 31;
    int leader = __ffs(m) - 1;
    unsigned tot = 0;
    #pragma unroll
    for (int j = 0; j < 32; j++) {
        unsigned bj = __shfl_sync(0xffffffffu, bin, j);
        unsigned wj = __shfl_sync(0xffffffffu, w, j);
        if (bj == bin) tot += wj;
    }
    if (bin < NB && lane == leader && tot > 0) atomicAdd(&bins[bin], tot);
}

// ------------------------- fused setup -------------------------
// [0,157): zero dirty; [157,733): repack; 733: csum; [734,1125): edge count
__global__ void k_setup(const float* __restrict__ convW,
                        const int* __restrict__ ei) {
    int blk = blockIdx.x, t = threadIdx.x;
    if (blk < 157) {
        int i = blk * 256 + t;
        if (i < NT) g_dirty[i] = 0;
        if (i == 0) g_nd = 0;
    } else if (blk < 733) {
        int idx = (blk - 157) * 256 + t;
        int l = idx / 49152;
        int rem = idx % 49152;
        int kk = rem / 192, j = rem % 192;
        int g = j >> 6, c = j & 63;
        g_Wcat[idx] = convW[(l * 768 + g * 256 + kk) * 64 + c];
    } else if (blk == 733) {
        if (t < 192) {
            int g = t >> 6, c = t & 63;
            float s = 0.0f;
            for (int k = 192; k < 256; k++) s += convW[(g * 256 + k) * 64 + c];
            g_csum[t] = s * sqrtf(1e-6f);
        }
    } else {
        int e = (blk - 734) * 256 + t;
        if (e < EDOUB) {
            int dst = ei[(e + EORIG) % EDOUB];
            atomicAdd(&g_cnt[dst], 1);
        }
    }
}

// Partial log-sums + (last block) prefix scan / pna / cnt-reset. Grid 40.
__global__ void k_scanA() {
    __shared__ float ws[8];
    __shared__ int lastf;
    int t = threadIdx.x;
    int i = blockIdx.x * 256 + t;
    float v = (i < NN) ? logf((float)g_cnt[i] + 1.0f) : 0.0f;
    #pragma unroll
    for (int off = 16; off > 0; off >>= 1)
        v += __shfl_down_sync(0xffffffffu, v, off);
    if ((t & 31) == 0) ws[t >> 5] = v;
    __syncthreads();
    if (t == 0) {
        float s = 0.0f;
        #pragma unroll
        for (int w = 0; w < 8; w++) s += ws[w];
        g_partial[blockIdx.x] = s;
    }
    __threadfence();
    if (t == 0) lastf = (atomicAdd(&g_ticket, 1) == (int)gridDim.x - 1);
    __syncthreads();
    if (!lastf) return;
    __shared__ unsigned wsum[8];
    int lane = t & 31, wid = t >> 5;
    int base = t * 40;
    unsigned s = 0;
    for (int j = 0; j < 40; j++) {
        int idx = base + j;
        if (idx < NN) s += (unsigned)g_cnt[idx];
    }
    unsigned sc = s;
    #pragma unroll
    for (int off = 1; off < 32; off <<= 1) {
        unsigned vv = __shfl_up_sync(0xffffffffu, sc, off);
        if (lane >= off) sc += vv;
    }
    if (lane == 31) wsum[wid] = sc;
    __syncthreads();
    if (wid == 0 && lane < 8) {
        unsigned vv = wsum[lane];
        #pragma unroll
        for (int off = 1; off < 8; off <<= 1) {
            unsigned u2 = __shfl_up_sync(0xFFu, vv, off);
            if (lane >= off) vv += u2;
        }
        wsum[lane] = vv;
    }
    __syncthreads();
    unsigned run = sc - s + (wid ? wsum[wid - 1] : 0u);
    for (int j = 0; j < 40; j++) {
        int idx = base + j;
        if (idx < NN) {
            unsigned c = (unsigned)g_cnt[idx];
            g_ptr[idx] = (int)run; g_cur[idx] = (int)run; run += c;
            g_cnt[idx] = 0;
        }
    }
    if (t == 255) g_ptr[NN] = (int)wsum[7];
    if (t == 0) {
        float p = 0.0f;
        for (int w = 0; w < 40; w++) p += g_partial[w];
        g_pna = p / (float)NN;
        g_ticket = 0;
    }
}

__global__ void k_scatter(const int* __restrict__ ei, const int* __restrict__ ea) {
    int e = blockIdx.x * blockDim.x + threadIdx.x;
    if (e >= EDOUB) return;
    int src = ei[e];
    int dst = ei[(e + EORIG) % EDOUB];
    int a   = ea[e % EORIG];
    int pos = atomicAdd(&g_cur[dst], 1);
    g_adj[pos] = src | (a << 16);
}

// ------------------------- fused prep (256 threads, smem-staged baseB) ----
__global__ void k_prep(const int* __restrict__ h_index,
                       const int* __restrict__ r_index,
                       const float* __restrict__ hstates,
                       const float* __restrict__ relT,
                       const float* __restrict__ Wlin,
                       const float* __restrict__ blin,
                       const float* __restrict__ W1,
                       const float* __restrict__ b1,
                       const float* __restrict__ W2,
                       const float* __restrict__ b2,
                       const float* __restrict__ convb) {   // 256 threads
    int blk = blockIdx.x, t = threadIdx.x;
    if (blk < 64) {
        extern __shared__ float dsm[];
        float* WlinS = dsm;            // 128*64
        float* W1S   = dsm + 8192;     // 64*128
        __shared__ float sqp[64], supd[4][64], sx[4][64], sred[4][64];
        #pragma unroll
        for (int q = 0; q < 32; q++) WlinS[q * 256 + t] = Wlin[q * 256 + t];
        #pragma unroll
        for (int q = 0; q < 32; q++) W1S[q * 256 + t] = W1[q * 256 + t];
        int g = t >> 6, tt = t & 63;
        int r0 = r_index[0];
        __syncthreads();
        if (g == 0) {
            float acc = blin[tt];
            for (int d = 0; d < DD; d++)
                acc += relT[r0 * DD + d] * WlinS[(DD + d) * DD + tt];
            sqp[tt] = acc;
        }
        int deg = blk * 4 + g;
        float pna = g_pna;
        float sl = logf((float)deg + 1.0f);
        float amp = sl / pna;
        float att = pna / (sl + 1e-6f);
        {
            float u = g_csum[tt] + amp * g_csum[64 + tt] + att * g_csum[128 + tt] + convb[tt];
            supd[g][tt] = fmaxf(u, 0.0f);
        }
        __syncthreads();
        {
            float heur = sqp[tt];
            for (int d = 0; d < 64; d++) heur += supd[g][d] * WlinS[d * DD + tt];
            sx[g][tt] = supd[g][tt] * heur;
        }
        __syncthreads();
        {
            float p = 0.0f;
            #pragma unroll
            for (int oo = 0; oo < 2; oo++) {
                int o = tt * 2 + oo;
                float a = b1[o];
                for (int d = 0; d < 64; d++) a += sx[g][d] * W1S[d * 128 + o];
                p += fmaxf(a, 0.0f) * W2[o];
            }
            sred[g][tt] = p;
        }
        __syncthreads();
        for (int off = 32; off > 0; off >>= 1) {
            if (tt < off) sred[g][tt] += sred[g][tt + off];
            __syncthreads();
        }
        g_updB[deg * 64 + tt] = supd[g][tt];
        if (tt == 0) g_scoreB[deg] = sred[g][0] + b2[0];
    } else if (blk == 64) {
        if (t >= 128) return;
        __shared__ float sx2[4][64];
        int b = t >> 5, ln = t & 31;
        int r0 = r_index[b * 16];
        const float* hv = hstates + b * DD;
        const float* rv = relT + r0 * DD;
        #pragma unroll
        for (int half = 0; half < 2; half++) {
            int c = ln + half * 32;
            float acc = blin[c];
            for (int d = 0; d < DD; d++)
                acc += hv[d] * Wlin[d * DD + c] + rv[d] * Wlin[(DD + d) * DD + c];
            sx2[b][c] = hv[c] * acc;
        }
        __syncwarp();
        float sp = 0.0f;
        #pragma unroll
        for (int oo = 0; oo < 4; oo++) {
            int o = ln * 4 + oo;
            float a2 = b1[o];
            for (int d = 0; d < DD; d++) a2 += sx2[b][d] * W1[d * 128 + o];
            a2 = fmaxf(a2, 0.0f);
            sp += a2 * W2[o];
        }
        #pragma unroll
        for (int off = 16; off > 0; off >>= 1)
            sp += __shfl_down_sync(0xffffffffu, sp, off);
        if (ln == 0) g_headsc[b] = sp + b2[0];
    } else if (blk == 65) {
        if (t >= 128) return;
        int wb = t >> 5, ln = t & 31;
        int h = h_index[wb * 16];
        int p0 = g_ptr[h], p1 = g_ptr[h + 1];
        if (ln == 0) {
            int v = wb * NN + h;
            if (atomicExch(&g_dirty[v], 1) == 0) { int pos = atomicAdd(&g_nd, 1); g_dlist[pos] = v; }
        }
        for (int p = p0 + ln; p < p1; p += 32) {
            int u = g_adj[p] & 0xFFFF;
            int v = wb * NN + u;
            if (atomicExch(&g_dirty[v], 1) == 0) { int pos = atomicAdd(&g_nd, 1); g_dlist[pos] = v; }
        }
        __syncwarp();
        if (t == 0) g_wl = NN + g_nd;
    } else {
        if (t < DD) {
            int r0 = r_index[0];
            float acc = blin[t];
            for (int d = 0; d < DD; d++)
                acc += relT[r0 * DD + d] * Wlin[(DD + d) * DD + t];
            g_qpart[t] = acc;
        }
    }
}

// ------------------------- aggregation (float2 lanes) -------------------------
__device__ __forceinline__ void writeFeat2(int row, int lane, int deg,
                                           float s0, float s1, float q0, float q1,
                                           float mx0, float mx1, float mn0, float mn1) {
    int d = lane * 2;
    float fdeg = (float)deg;
    float den = fmaxf(fdeg, 1.0f);
    float me0 = s0 / den, me1 = s1 / den;
    float sd0 = sqrtf(fmaxf(q0 / den - me0 * me0, 0.0f) + 1e-6f);
    float sd1 = sqrtf(fmaxf(q1 / den - me1 * me1, 0.0f) + 1e-6f);
    if (deg == 0) { mx0 = 0; mx1 = 0; mn0 = 0; mn1 = 0; }
    float* F = g_feat + (size_t)row * 256;
    *(float2*)(F + d)       = make_float2(me0, me1);
    *(float2*)(F + 64 + d)  = make_float2(mx0, mx1);
    *(float2*)(F + 128 + d) = make_float2(mn0, mn1);
    *(float2*)(F + 192 + d) = make_float2(sd0, sd1);
    if (lane == 0) g_deg[row] = fdeg;
}

// blocks [0,1250): copy-0 base agg; [1250,1314): dirty agg (analytic layer-0 state)
__global__ void k_agg0(const float* __restrict__ text, const float* __restrict__ relw,
                       const int* __restrict__ h_index, const float* __restrict__ hstates) {
    int blk = blockIdx.x;
    int lane = threadIdx.x & 31;
    int d = lane * 2;
    const float* rw = relw;   // l = 0
    if (blk < 1250) {
        int v = blk * 8 + (threadIdx.x >> 5);
        if (v >= NN) return;
        int p0 = g_ptr[v], p1 = g_ptr[v + 1];
        float s0 = 0, s1 = 0, q0 = 0, q1 = 0;
        float mx0 = -INFINITY, mx1 = -INFINITY, mn0 = INFINITY, mn1 = INFINITY;
        int deg = 0;
        for (int p = p0; p < p1; p++) {
            int pk = __ldg(&g_adj[p]);
            int u = pk & 0xFFFF, a = pk >> 16;
            float2 tv = *(const float2*)(text + (size_t)u * DD + d);
            float2 rv = *(const float2*)(rw + a * DD + d);
            float m0 = 0.5f * tv.x * rv.x;
            float m1 = 0.5f * tv.y * rv.y;
            s0 += m0; q0 += m0 * m0; mx0 = fmaxf(mx0, m0); mn0 = fminf(mn0, m0);
            s1 += m1; q1 += m1 * m1; mx1 = fmaxf(mx1, m1); mn1 = fminf(mn1, m1);
            deg++;
        }
        writeFeat2(v, lane, deg, s0, s1, q0, q1, mx0, mx1, mn0, mn1);
    } else {
        int j = (blk - 1250) * 8 + (threadIdx.x >> 5);
        if (j >= g_nd) return;
        int v = g_dlist[j];
        int b = v / NN;
        int lv = v - b * NN;
        int hb = h_index[b * 16];
        float hsb = g_headsc[b];
        const float* hrow = hstates + b * DD;
        int p0 = g_ptr[lv], p1 = g_ptr[lv + 1];
        float s0 = 0, s1 = 0, q0 = 0, q1 = 0;
        float mx0 = -INFINITY, mx1 = -INFINITY, mn0 = INFINITY, mn1 = INFINITY;
        int deg = 0;
        for (int p = p0; p < p1; p++) {
            int pk = __ldg(&g_adj[p]);
            int u = pk & 0xFFFF, a = pk >> 16;
            bool ishead = (u == hb);
            float scu = ishead ? hsb : 0.0f;
            if (scu >= 0.0f) {
                float wgt = 1.0f / (1.0f + __expf(-scu));
                float h0v, h1v;
                if (ishead) { h0v = hrow[d]; h1v = hrow[d + 1]; }
                else if (b == 0) {
                    float2 tv = *(const float2*)(text + (size_t)u * DD + d);
                    h0v = tv.x; h1v = tv.y;
                } else { h0v = 0.0f; h1v = 0.0f; }
                float2 rv = *(const float2*)(rw + a * DD + d);
                float m0 = wgt * h0v * rv.x;
                float m1 = wgt * h1v * rv.y;
                s0 += m0; q0 += m0 * m0; mx0 = fmaxf(mx0, m0); mn0 = fminf(mn0, m0);
                s1 += m1; q1 += m1 * m1; mx1 = fmaxf(mx1, m1); mn1 = fminf(mn1, m1);
                deg++;
            }
        }
        writeFeat2(NN + j, lane, deg, s0, s1, q0, q1, mx0, mx1, mn0, mn1);
    }
}

// ---------- selection + aggregation megakernel (layers 1-2) ---------------
// 157 blocks, 256 thr, small footprint (>=4 blocks/SM) -> all-resident safe.
// Phases 0-2: dual-threshold radix select (release/ticket barrier).
// Phase 3: worklist + aggregation, warp-strided; kernel boundary drains.
__global__ void k_selagg(const float* __restrict__ relw, int l) {
    int t = threadIdx.x;
    __shared__ int lastf;
    __shared__ unsigned ss[256];
    __shared__ unsigned rBin, rKrem;
    __shared__ float sThr, sTw;
    __shared__ unsigned relbase;
    if (t == 0) relbase = *((volatile unsigned*)&g_release);
    __syncthreads();

    for (int pass = 0; pass < 3; pass++) {
        const int shift = (pass == 0) ? 21 : (pass == 1) ? 10 : 0;
        const unsigned nb = (pass == 2) ? 1024u : 2048u;
        unsigned prefC = 0, prefW = 0;
        if (pass > 0) { prefC = g_prefixC; prefW = g_prefixW; }
        int i = blockIdx.x * 256 + t;
        unsigned binC = 0xFFFFFFFFu, binW = 0xFFFFFFFFu, w = 0;
        if (i < NT) {
            unsigned key = f2key(g_score[i]);
            int lv = i - (i / NN) * NN;
            w = (unsigned)(g_ptr[lv + 1] - g_ptr[lv]);
            bool mC, mW;
            if (pass == 0) { mC = true; mW = true; }
            else if (pass == 1) { mC = ((key >> 21) == (prefC >> 21)); mW = ((key >> 21) == (prefW >> 21)); }
            else { mC = ((key >> 10) == (prefC >> 10)); mW = ((key >> 10) == (prefW >> 10)); }
            unsigned bb = (key >> shift) & (nb - 1u);
            if (mC) binC = bb;
            if (mW) binW = bb;
        }
        warpHistAdd(g_binsA, binC, 1, nb);
        warpHistAdd(g_binsB, binW, w, nb);
        __threadfence();
        if (t == 0) lastf = (atomicAdd(&g_ticket, 1) == SELB * (pass + 1) - 1);
        __syncthreads();

        if (lastf) {
            const int chunk = (int)(nb >> 8);
            {
                unsigned loc[8]; unsigned s = 0;
                #pragma unroll
                for (int j = 0; j < 8; j++) { loc[j] = (j < chunk) ? g_binsA[t * chunk + j] : 0u; s += loc[j]; }
                ss[t] = s;
                __syncthreads();
                for (int off = 1; off < 256; off <<= 1) {
                    unsigned v = (t + off < 256) ? ss[t + off] : 0u;
                    __syncthreads();
                    ss[t] += v;
                    __syncthreads();
                }
                unsigned kk = (pass == 0) ? KS_N : g_kremC;
                unsigned cumTop = (t < 255) ? ss[t + 1] : 0u;
                if (cumTop < kk && cumTop + s >= kk) {
                    unsigned c = cumTop;
                    for (int j = chunk - 1; j >= 0; j--) {
                        if (c + loc[j] >= kk) { rBin = (unsigned)(t * chunk + j); rKrem = kk - c; break; }
                        c += loc[j];
                    }
                }
                __syncthreads();
                if (t == 0) {
                    unsigned npref = prefC | (rBin << shift);
                    if (pass < 2) { g_prefixC = npref; g_kremC = rKrem; }
                    else sThr = key2f(npref);
                }
                __syncthreads();
            }
            {
                unsigned loc[8]; unsigned s = 0;
                #pragma unroll
                for (int j = 0; j < 8; j++) { loc[j] = (j < chunk) ? g_binsB[t * chunk + j] : 0u; s += loc[j]; }
                ss[t] = s;
                __syncthreads();
                for (int off = 1; off < 256; off <<= 1) {
                    unsigned v = (t + off < 256) ? ss[t + off] : 0u;
                    __syncthreads();
                    ss[t] += v;
                    __syncthreads();
                }
                unsigned kk = (pass == 0) ? ES_E : g_kremW;
                unsigned cumTop = (t < 255) ? ss[t + 1] : 0u;
                if (cumTop < kk && cumTop + s >= kk) {
                    unsigned c = cumTop;
                    for (int j = chunk - 1; j >= 0; j--) {
                        if (c + loc[j] >= kk) { rBin = (unsigned)(t * chunk + j); rKrem = kk - c; break; }
                        c += loc[j];
                    }
                }
                __syncthreads();
                if (t == 0) {
                    unsigned npref = prefW | (rBin << shift);
                    if (pass < 2) { g_prefixW = npref; g_kremW = rKrem; }
                    else sTw = key2f(npref);
                }
                __syncthreads();
            }
            #pragma unroll
            for (int j = 0; j < 8; j++)
                if (j < chunk) { g_binsA[t * chunk + j] = 0; g_binsB[t * chunk + j] = 0; }
            __syncthreads();
            if (t == 0) {
                if (pass == 2) {
                    g_thr = sThr; g_T = fmaxf(sThr, sTw); g_wl = 0;
                    g_ticket = 0;
                }
                __threadfence();
                atomicExch(&g_release, relbase + (unsigned)(pass + 1));
            }
            __syncthreads();
        } else {
            if (t == 0) {
                while (*((volatile unsigned*)&g_release) < relbase + (unsigned)(pass + 1))
                    __nanosleep(64);
            }
            __syncthreads();
            __threadfence();
        }
    }

    // ---- phase 3: worklist + aggregation (warp-strided; no end barrier) ----
    {
        int lane = t & 31;
        int d = lane * 2;
        float T = *((volatile float*)&g_T);
        const float* rw = relw + l * 400 * DD;
        for (int i = blockIdx.x * 8 + (t >> 5); i < NT; i += SELB * 8) {
            int base = (i / NN) * NN;
            int lv = i - base;
            int p0 = g_ptr[lv], p1 = g_ptr[lv + 1];
            if (p1 == p0 || !(g_score[i] >= T)) continue;
            int row = 0;
            if (lane == 0) row = atomicAdd(&g_wl, 1);
            row = __shfl_sync(0xffffffffu, row, 0);
            float s0 = 0, s1 = 0, q0 = 0, q1 = 0;
            float mx0 = -INFINITY, mx1 = -INFINITY, mn0 = INFINITY, mn1 = INFINITY;
            int deg = 0;
            for (int p = p0; p < p1; p++) {
                int pk = __ldg(&g_adj[p]);
                int u = pk & 0xFFFF, a = pk >> 16;
                int gu = base + u;
                float sc = g_score[gu];
                if (sc >= T) {
                    float wgt = 1.0f / (1.0f + __expf(-sc));
                    float2 hv = *(const float2*)(g_hidden + (size_t)gu * DD + d);
                    float2 rv = *(const float2*)(rw + a * DD + d);
                    float m0 = wgt * hv.x * rv.x;
                    float m1 = wgt * hv.y * rv.y;
                    s0 += m0; q0 += m0 * m0; mx0 = fmaxf(mx0, m0); mn0 = fminf(mn0, m0);
                    s1 += m1; q1 += m1 * m1; mx1 = fmaxf(mx1, m1); mn1 = fminf(mn1, m1);
                    deg++;
                }
            }
            writeFeat2(row, lane, deg, s0, s1, q0, q1, mx0, mx1, mn0, mn1);
            if (lane == 0) g_wlist[row] = i;
        }
    }
}

// Layer-0 GEMM: C[cnt,192] = feat[cnt,256] @ Wcat[256,192]; 128x64 tile, 8x4 micro
__global__ void k_gemm(int l) {
    __shared__ float sA[16 * 128];
    __shared__ float sB[16 * 64];
    int cnt = g_wl;
    int rowBase = blockIdx.x * 128;
    if (rowBase >= cnt) return;
    int colBase = blockIdx.y * 64;
    int t = threadIdx.x;
    int tx = t & 15, ty = t >> 4;
    const float* Wb = g_Wcat + l * 256 * 192;
    float acc[8][4] = {};
    for (int k0 = 0; k0 < 256; k0 += 16) {
        #pragma unroll
        for (int q = 0; q < 2; q++) {
            int lin = t * 2 + q;
            int r = lin >> 2, kq = lin & 3;
            float4 av = make_float4(0, 0, 0, 0);
            int row = rowBase + r;
            if (row < cnt) av = *(const float4*)(g_feat + (size_t)row * 256 + k0 + kq * 4);
            sA[(kq * 4 + 0) * 128 + r] = av.x;
            sA[(kq * 4 + 1) * 128 + r] = av.y;
            sA[(kq * 4 + 2) * 128 + r] = av.z;
            sA[(kq * 4 + 3) * 128 + r] = av.w;
        }
        {
            int kb = t >> 4, j4 = (t & 15) * 4;
            float4 bv = *(const float4*)(Wb + (size_t)(k0 + kb) * 192 + colBase + j4);
            *(float4*)&sB[kb * 64 + j4] = bv;
        }
        __syncthreads();
        #pragma unroll
        for (int kk = 0; kk < 16; kk++) {
            float4 a0 = *(float4*)&sA[kk * 128 + ty * 8];
            float4 a1 = *(float4*)&sA[kk * 128 + ty * 8 + 4];
            float4 b0 = *(float4*)&sB[kk * 64 + tx * 4];
            float a[8] = {a0.x, a0.y, a0.z, a0.w, a1.x, a1.y, a1.z, a1.w};
            float bb[4] = {b0.x, b0.y, b0.z, b0.w};
            #pragma unroll
            for (int i = 0; i < 8; i++)
                #pragma unroll
                for (int j = 0; j < 4; j++)
                    acc[i][j] += a[i] * bb[j];
        }
        __syncthreads();
    }
    #pragma unroll
    for (int i = 0; i < 8; i++) {
        int row = rowBase + ty * 8 + i;
        if (row < cnt) {
            float4 v = make_float4(acc[i][0], acc[i][1], acc[i][2], acc[i][3]);
            *(float4*)(g_C + (size_t)row * 192 + colBase + tx * 4) = v;
        }
    }
}

// Layers 1-2 fused GEMM + post. 64 rows/block, grid 128.
__global__ void k_gp(const float* __restrict__ convb,
                     const float* __restrict__ Wlin,
                     const float* __restrict__ W1,
                     const float* __restrict__ b1,
                     const float* __restrict__ W2,
                     const float* __restrict__ b2, int l) {
    extern __shared__ float smem[];
    float* sC   = smem;                   // 64*192
    float* sh   = sC + 64 * 192;          // 64*65
    float* sbuf = sh + 64 * 65;           // 64*128
    float* sqp  = sbuf + 64 * 128;
    float* samp = sqp + 64;
    float* satt = samp + 64;
    float* sw2  = satt + 64;
    float* sb1  = sw2 + 128;
    int*   sv   = (int*)(sb1 + 128);      // 64
    float* sA   = (float*)(sv + 64);      // 16*64
    float* sB   = sA + 16 * 64;           // 16*192

    int cnt = g_wl;
    int rowBase = blockIdx.x * 64;
    if (rowBase >= cnt) return;
    int t = threadIdx.x;
    int tx = t & 15, ty = t >> 4;

    if (t < 64) {
        int i = rowBase + t;
        float dg = (i < cnt) ? g_deg[i] : 0.0f;
        float sl = logf(dg + 1.0f);
        float pna = g_pna;
        samp[t] = sl / pna;
        satt[t] = pna / (sl + 1e-6f);
        sv[t] = (i < cnt) ? g_wlist[i] : -1;
        sqp[t] = g_qpart[t];
    }
    if (t < 128) { sw2[t] = W2[t]; sb1[t] = b1[t]; }

    const float* Wb = g_Wcat + l * 256 * 192;
    float acc[4][12] = {};
    for (int k0 = 0; k0 < 256; k0 += 16) {
        {
            int r = t >> 2, kq = t & 3;
            int row = rowBase + r;
            float4 av = make_float4(0, 0, 0, 0);
            if (row < cnt) av = *(const float4*)(g_feat + (size_t)row * 256 + k0 + kq * 4);
            sA[(kq * 4 + 0) * 64 + r] = av.x;
            sA[(kq * 4 + 1) * 64 + r] = av.y;
            sA[(kq * 4 + 2) * 64 + r] = av.z;
            sA[(kq * 4 + 3) * 64 + r] = av.w;
        }
        #pragma unroll
        for (int q = 0; q < 3; q++) {
            int lin = q * 256 + t;
            int kb = lin / 48, c4 = (lin % 48) * 4;
            float4 bv = *(const float4*)(Wb + (size_t)(k0 + kb) * 192 + c4);
            *(float4*)&sB[kb * 192 + c4] = bv;
        }
        __syncthreads();
        #pragma unroll
        for (int kk = 0; kk < 16; kk++) {
            float a[4];
            #pragma unroll
            for (int i = 0; i < 4; i++) a[i] = sA[kk * 64 + ty * 4 + i];
            float b[12];
            #pragma unroll
            for (int q = 0; q < 3; q++) {
                float4 b4 = *(float4*)&sB[kk * 192 + tx * 12 + q * 4];
                b[q * 4 + 0] = b4.x; b[q * 4 + 1] = b4.y;
                b[q * 4 + 2] = b4.z; b[q * 4 + 3] = b4.w;
            }
            #pragma unroll
            for (int i = 0; i < 4; i++)
                #pragma unroll
                for (int j = 0; j < 12; j++)
                    acc[i][j] += a[i] * b[j];
        }
        __syncthreads();
    }
    #pragma unroll
    for (int i = 0; i < 4; i++)
        #pragma unroll
        for (int j = 0; j < 12; j++)
            sC[(ty * 4 + i) * 192 + tx * 12 + j] = acc[i][j];
    __syncthreads();

    #pragma unroll
    for (int q = 0; q < 16; q++) {
        int lin = t + q * 256;
        int r = lin >> 6, dd = lin & 63;
        int i = rowBase + r;
        float nh = 0.0f;
        if (i < cnt) {
            const float* C = sC + r * 192;
            float u = C[dd] + samp[r] * C[64 + dd] + satt[r] * C[128 + dd] + convb[l * 64 + dd];
            u = fmaxf(u, 0.0f);
            int v = sv[r];
            nh = g_hidden[(size_t)v * DD + dd] + u;
            g_hidden[(size_t)v * DD + dd] = nh;
        }
        sh[r * 65 + dd] = nh;
    }
    #pragma unroll
    for (int q = 0; q < 16; q++) {
        int lin = t + q * 256;
        int r = lin >> 6, c = lin & 63;
        sbuf[r * 68 + c] = Wlin[r * DD + c];
    }
    __syncthreads();

    {
        float acc2[4][4] = {};
        for (int k = 0; k < 64; k++) {
            float a[4], bb[4];
            #pragma unroll
            for (int i = 0; i < 4; i++) a[i] = sh[(ty * 4 + i) * 65 + k];
            float4 b4 = *(float4*)&sbuf[k * 68 + tx * 4];
            bb[0] = b4.x; bb[1] = b4.y; bb[2] = b4.z; bb[3] = b4.w;
            #pragma unroll
            for (int i = 0; i < 4; i++)
                #pragma unroll
                for (int j = 0; j < 4; j++)
                    acc2[i][j] += a[i] * bb[j];
        }
        __syncthreads();
        #pragma unroll
        for (int i = 0; i < 4; i++)
            #pragma unroll
            for (int j = 0; j < 4; j++) {
                int r = ty * 4 + i, c = tx * 4 + j;
                float hv = sh[r * 65 + c];
                sh[r * 65 + c] = hv * (acc2[i][j] + sqp[c]);
            }
        __syncthreads();
    }

    #pragma unroll
    for (int q = 0; q < 32; q++) {
        int lin = t + q * 256;
        sbuf[lin] = W1[lin];
    }
    __syncthreads();

    {
        float acc3[4][8] = {};
        for (int k = 0; k < 64; k++) {
            float a[4];
            #pragma unroll
            for (int i = 0; i < 4; i++) a[i] = sh[(ty * 4 + i) * 65 + k];
            float4 b0 = *(float4*)&sbuf[k * 128 + tx * 8];
            float4 b1v = *(float4*)&sbuf[k * 128 + tx * 8 + 4];
            float bb[8] = {b0.x, b0.y, b0.z, b0.w, b1v.x, b1v.y, b1v.z, b1v.w};
            #pragma unroll
            for (int i = 0; i < 4; i++)
                #pragma unroll
                for (int j = 0; j < 8; j++)
                    acc3[i][j] += a[i] * bb[j];
        }
        float bias2 = b2[0];
        #pragma unroll
        for (int i = 0; i < 4; i++) {
            float p = 0.0f;
            #pragma unroll
            for (int j = 0; j < 8; j++) {
                int o = tx * 8 + j;
                p += fmaxf(acc3[i][j] + sb1[o], 0.0f) * sw2[o];
            }
            p += __shfl_xor_sync(0xffffffffu, p, 1);
            p += __shfl_xor_sync(0xffffffffu, p, 2);
            p += __shfl_xor_sync(0xffffffffu, p, 4);
            p += __shfl_xor_sync(0xffffffffu, p, 8);
            if ((t & 15) == 0) {
                int i2 = rowBase + ty * 4 + i;
                if (i2 < cnt) {
                    int v = sv[ty * 4 + i];
                    g_score[v] = p + bias2;
                }
            }
        }
    }
}

// Layer-0 post + broadcast. blocks [0,165) post0 (reads g_C); [165,2040) bcast.
__global__ void k_post0x(const float* __restrict__ text,
                         const float* __restrict__ convb,
                         const float* __restrict__ Wlin,
                         const float* __restrict__ W1,
                         const float* __restrict__ b1,
                         const float* __restrict__ W2,
                         const float* __restrict__ b2,
                         const int* __restrict__ h_index,
                         const float* __restrict__ hstates) {
    int t = threadIdx.x;
    if (blockIdx.x >= 165) {
        int idx = (blockIdx.x - 165) * 256 + t;
        if (idx >= 3 * NN * 16) return;
        int v = NN + (idx >> 4), q = idx & 15;
        if (g_dirty[v]) return;
        int lv = v - (v / NN) * NN;
        int deg = g_ptr[lv + 1] - g_ptr[lv];
        float4 uv = make_float4(0, 0, 0, 0);
        float scv = 0.0f;
        if (deg > 0) {
            int dc = min(deg, 255);
            uv = *(const float4*)(g_updB + dc * 64 + q * 4);
            scv = g_scoreB[dc];
        }
        *(float4*)(g_hidden + (size_t)v * DD + q * 4) = uv;
        if (q == 0) g_score[v] = scv;
        return;
    }
    extern __shared__ float smem[];
    float* sh   = smem;
    float* sbuf = smem + 64 * 65;
    float* sqp  = sbuf + 64 * 128;
    float* samp = sqp + 64;
    float* satt = samp + 64;
    float* sw2  = satt + 64;
    float* sb1  = sw2 + 128;
    float* ss0  = sb1 + 128;
    int*   svg  = (int*)(ss0 + 64);
    int*   som  = svg + 64;

    int cnt = g_wl;
    int rowBase = blockIdx.x * 64;
    if (rowBase >= cnt) return;

    if (t < 64) {
        int i = rowBase + t;
        float dg = 0.0f; int vg = 0; int flags = 0; float sc0 = 0.0f;
        if (i < cnt) {
            dg = g_deg[i];
            if (i < NN) {
                vg = i;
                flags = 2 | ((g_ptr[i + 1] > g_ptr[i]) ? 1 : 0) | (g_dirty[i] ? 4 : 0);
            } else {
                int v = g_dlist[i - NN]; vg = v;
                int b = v / NN;
                int lv = v - b * NN;
                int sdeg = g_ptr[lv + 1] - g_ptr[lv];
                int hb = h_index[b * 16];
                bool ishead = (lv == hb);
                float hs = ishead ? g_headsc[b] : 0.0f;
                sc0 = hs;
                flags = ((hs >= 0.0f) && sdeg > 0) ? 1 : 0;
                if (ishead) flags |= 8;
            }
        }
        float sl = logf(dg + 1.0f);
        float pna = g_pna;
        samp[t] = sl / pna;
        satt[t] = pna / (sl + 1e-6f);
        svg[t] = vg; som[t] = flags; ss0[t] = sc0;
        sqp[t] = g_qpart[t];
    }
    if (t < 128) { sw2[t] = W2[t]; sb1[t] = b1[t]; }
    __syncthreads();

    #pragma unroll
    for (int q = 0; q < 16; q++) {
        int lin = t + q * 256;
        int r = lin >> 6, dd = lin & 63;
        int i = rowBase + r;
        float nh = 0.0f;
        if (i < cnt) {
            int flags = som[r]; int vg = svg[r];
            float pre;
            if (flags & 2) pre = text[(size_t)vg * DD + dd];
            else {
                int b = vg / NN; int lv = vg - b * NN;
                if (flags & 8) pre = hstates[b * DD + dd];
                else pre = (b == 0) ? text[(size_t)lv * DD + dd] : 0.0f;
            }
            float u = 0.0f;
            if (flags & 1) {
                const float* C = g_C + (size_t)i * 192;
                u = fmaxf(C[dd] + samp[r] * C[64 + dd] + satt[r] * C[128 + dd] + convb[dd], 0.0f);
            }
            nh = pre + u;
            if (flags & 2) {
                if (!(flags & 4)) g_hidden[(size_t)vg * DD + dd] = nh;
            } else {
                g_hidden[(size_t)vg * DD + dd] = nh;
            }
        }
        sh[r * 65 + dd] = nh;
    }
    #pragma unroll
    for (int q = 0; q < 16; q++) {
        int lin = t + q * 256;
        int r = lin >> 6, c = lin & 63;
        sbuf[r * 68 + c] = Wlin[r * DD + c];
    }
    __syncthreads();

    int tx = t & 15, ty = t >> 4;
    {
        float acc[4][4] = {};
        for (int k = 0; k < 64; k++) {
            float a[4], bb[4];
            #pragma unroll
            for (int i = 0; i < 4; i++) a[i] = sh[(ty * 4 + i) * 65 + k];
            float4 b4 = *(float4*)&sbuf[k * 68 + tx * 4];
            bb[0] = b4.x; bb[1] = b4.y; bb[2] = b4.z; bb[3] = b4.w;
            #pragma unroll
            for (int i = 0; i < 4; i++)
                #pragma unroll
                for (int j = 0; j < 4; j++)
                    acc[i][j] += a[i] * bb[j];
        }
        __syncthreads();
        #pragma unroll
        for (int i = 0; i < 4; i++)
            #pragma unroll
            for (int j = 0; j < 4; j++) {
                int r = ty * 4 + i, c = tx * 4 + j;
                float hv = sh[r * 65 + c];
                sh[r * 65 + c] = hv * (acc[i][j] + sqp[c]);
            }
        __syncthreads();
    }

    #pragma unroll
    for (int q = 0; q < 32; q++) {
        int lin = t + q * 256;
        sbuf[lin] = W1[lin];
    }
    __syncthreads();

    {
        float acc[4][8] = {};
        for (int k = 0; k < 64; k++) {
            float a[4];
            #pragma unroll
            for (int i = 0; i < 4; i++) a[i] = sh[(ty * 4 + i) * 65 + k];
            float4 b0 = *(float4*)&sbuf[k * 128 + tx * 8];
            float4 b1v = *(float4*)&sbuf[k * 128 + tx * 8 + 4];
            float bb[8] = {b0.x, b0.y, b0.z, b0.w, b1v.x, b1v.y, b1v.z, b1v.w};
            #pragma unroll
            for (int i = 0; i < 4; i++)
                #pragma unroll
                for (int j = 0; j < 8; j++)
                    acc[i][j] += a[i] * bb[j];
        }
        float bias2 = b2[0];
        #pragma unroll
        for (int i = 0; i < 4; i++) {
            float p = 0.0f;
            #pragma unroll
            for (int j = 0; j < 8; j++) {
                int o = tx * 8 + j;
                p += fmaxf(acc[i][j] + sb1[o], 0.0f) * sw2[o];
            }
            p += __shfl_xor_sync(0xffffffffu, p, 1);
            p += __shfl_xor_sync(0xffffffffu, p, 2);
            p += __shfl_xor_sync(0xffffffffu, p, 4);
            p += __shfl_xor_sync(0xffffffffu, p, 8);
            if ((t & 15) == 0) {
                int i2 = rowBase + ty * 4 + i;
                if (i2 < cnt) {
                    int rr = ty * 4 + i;
                    int flags = som[rr];
                    int vg = svg[rr];
                    float sc = p + bias2;
                    if (flags & 2) {
                        if (!(flags & 4)) g_score[vg] = (flags & 1) ? sc : 0.0f;
                    } else {
                        g_score[vg] = (flags & 1) ? sc : ss0[rr];
                    }
                }
            }
        }
    }
}

__global__ void k_out(const int* __restrict__ t_index, float* __restrict__ out) {
    int t = threadIdx.x;
    if (t >= 64) return;
    int b = t / 16;
    int v = t_index[t] + b * NN;
    out[t] = g_score[v];
}

// ------------------------- launch -------------------------
extern "C" void kernel_launch(void* const* d_in, const int* in_sizes, int n_in,
                              void* d_out, int out_size) {
    const int*   h_index   = (const int*)d_in[0];
    const int*   r_index   = (const int*)d_in[1];
    const int*   t_index   = (const int*)d_in[2];
    const float* hstates   = (const float*)d_in[3];
    const int*   edge_idx  = (const int*)d_in[5];
    const int*   edge_attr = (const int*)d_in[6];
    const float* text      = (const float*)d_in[7];
    const float* relT      = (const float*)d_in[9];
    const float* Wlin      = (const float*)d_in[10];
    const float* blin      = (const float*)d_in[11];
    const float* W1        = (const float*)d_in[12];
    const float* b1        = (const float*)d_in[13];
    const float* W2        = (const float*)d_in[14];
    const float* b2        = (const float*)d_in[15];
    const float* relw      = (const float*)d_in[16];
    const float* convW     = (const float*)d_in[17];
    const float* convb     = (const float*)d_in[18];
    float* out = (float*)d_out;

    const int SMEM_POST0 = (64 * 65 + 64 * 128 + 64 * 3 + 128 * 2 + 64 + 128) * 4;
    const int SMEM_GP    = (64 * 192 + 64 * 65 + 64 * 128 + 64 * 3 + 128 * 2 + 64
                            + 16 * 64 + 16 * 192) * 4;
    const int SMEM_PREP  = (8192 + 8192) * 4;
    static int attr_done = 0;
    if (!attr_done) {
        cudaFuncSetAttribute(k_post0x, cudaFuncAttributeMaxDynamicSharedMemorySize, SMEM_POST0);
        cudaFuncSetAttribute(k_gp, cudaFuncAttributeMaxDynamicSharedMemorySize, SMEM_GP);
        cudaFuncSetAttribute(k_prep, cudaFuncAttributeMaxDynamicSharedMemorySize, SMEM_PREP);
        attr_done = 1;
    }

    k_setup<<<1125, 256>>>(convW, edge_idx);
    k_scanA<<<40, 256>>>();
    k_scatter<<<391, 256>>>(edge_idx, edge_attr);
    k_prep<<<67, 256, SMEM_PREP>>>(h_index, r_index, hstates, relT, Wlin, blin, W1, b1, W2, b2, convb);

    // ---- layer 0 (thr = T = 0 statically; analytic init state) ----
    k_agg0<<<1314, 256>>>(text, relw, h_index, hstates);
    k_gemm<<<dim3(83, 3), 256>>>(0);
    k_post0x<<<2040, 256, SMEM_POST0>>>(text, convb, Wlin, W1, b1, W2, b2, h_index, hstates);

    // ---- layers 1-2: selection + aggregation fused; then GEMM+post ----
    for (int l = 1; l < 3; l++) {
        k_selagg<<<SELB, 256>>>(relw, l);
        k_gp<<<128, 256, SMEM_GP>>>(convb, Wlin, W1, b1, W2, b2, l);
    }
    k_out<<<1, 64>>>(t_index, out);
}

// round 17
// speedup vs baseline: 1.2096x; 1.2096x over previous
#include <cuda_runtime.h>
#include <math.h>

#define NN 10000
#define EORIG 50000
#define EDOUB 100000
#define BB 4
#define NT 40000
#define DD 64
#define KS_N 4000u
#define ES_E 40000u
#define SELB 157

// ------------------------- device scratch (zero-initialized at load) ------
__device__ float g_hidden[NT * DD];
__device__ float g_score[NT];
__device__ float g_feat[NT * 256];
__device__ float g_C[NT * 192];
__device__ float g_Wcat[3 * 256 * 192];
__device__ float g_qpart[DD];
__device__ float g_deg[NT];
__device__ float g_csum[192];
__device__ float g_updB[256 * 64];
__device__ float g_scoreB[256];
__device__ float g_partial[40];
__device__ float g_headsc[4];
__device__ int   g_ptr[NN + 1];
__device__ int   g_cur[NN];
__device__ int   g_cnt[NN];
__device__ int   g_adj[EDOUB];
__device__ int   g_wlist[NT];
__device__ int   g_dirty[NT];
__device__ int   g_dlist[512];
__device__ int   g_nd;
__device__ unsigned g_binsA[2048];
__device__ unsigned g_binsB[2048];
__device__ float g_pna;
__device__ float g_thr;
__device__ float g_T;
__device__ unsigned g_prefixC, g_kremC, g_prefixW, g_kremW;
__device__ int g_wl;
__device__ int g_ticket;
__device__ unsigned g_release;

// ------------------------- helpers -------------------------
__device__ __forceinline__ unsigned f2key(float f) {
    unsigned u = __float_as_uint(f);
    return (u & 0x80000000u) ? ~u : (u | 0x80000000u);
}
__device__ __forceinline__ float key2f(unsigned key) {
    unsigned u = (key & 0x80000000u) ? (key & 0x7FFFFFFFu) : ~key;
    return __uint_as_float(u);
}

__device__ __forceinline__ void warpHistAdd(unsigned* bins, unsigned bin, unsigned w, unsigned NB) {
    unsigned m = __match_any_sync(0xffffffffu, bin);
    int lane = threadIdx.x & 31;
    int leader = __ffs(m) - 1;
    unsigned tot = 0;
    #pragma unroll
    for (int j = 0; j < 32; j++) {
        unsigned bj = __shfl_sync(0xffffffffu, bin, j);
        unsigned wj = __shfl_sync(0xffffffffu, w, j);
        if (bj == bin) tot += wj;
    }
    if (bin < NB && lane == leader && tot > 0) atomicAdd(&bins[bin], tot);
}

// ------------------------- fused setup -------------------------
// [0,157): zero dirty; [157,733): repack; 733: csum; [734,1125): edge count
__global__ void k_setup(const float* __restrict__ convW,
                        const int* __restrict__ ei) {
    int blk = blockIdx.x, t = threadIdx.x;
    if (blk < 157) {
        int i = blk * 256 + t;
        if (i < NT) g_dirty[i] = 0;
        if (i == 0) g_nd = 0;
    } else if (blk < 733) {
        int idx = (blk - 157) * 256 + t;
        int l = idx / 49152;
        int rem = idx % 49152;
        int kk = rem / 192, j = rem % 192;
        int g = j >> 6, c = j & 63;
        g_Wcat[idx] = convW[(l * 768 + g * 256 + kk) * 64 + c];
    } else if (blk == 733) {
        if (t < 192) {
            int g = t >> 6, c = t & 63;
            float s = 0.0f;
            for (int k = 192; k < 256; k++) s += convW[(g * 256 + k) * 64 + c];
            g_csum[t] = s * sqrtf(1e-6f);
        }
    } else {
        int e = (blk - 734) * 256 + t;
        if (e < EDOUB) {
            int dst = ei[(e + EORIG) % EDOUB];
            atomicAdd(&g_cnt[dst], 1);
        }
    }
}

// grid-wide deterministic partial sums of log(cnt+1)
__global__ void k_scanA() {   // grid 40, block 256
    __shared__ float ws[8];
    int t = threadIdx.x;
    int i = blockIdx.x * 256 + t;
    float v = (i < NN) ? logf((float)g_cnt[i] + 1.0f) : 0.0f;
    #pragma unroll
    for (int off = 16; off > 0; off >>= 1)
        v += __shfl_down_sync(0xffffffffu, v, off);
    if ((t & 31) == 0) ws[t >> 5] = v;
    __syncthreads();
    if (t == 0) {
        float s = 0.0f;
        #pragma unroll
        for (int w = 0; w < 8; w++) s += ws[w];
        g_partial[blockIdx.x] = s;
    }
}

// prefix sums (shuffle-based) + pna finalize + g_cnt re-zero for next call
__global__ void k_scan() {  // 1 block, 1024 threads
    __shared__ unsigned wsum[32];
    int t = threadIdx.x, lane = t & 31, wid = t >> 5;
    unsigned loc[10];
    unsigned s = 0;
    #pragma unroll
    for (int i = 0; i < 10; i++) {
        int idx = t * 10 + i;
        unsigned c = (idx < NN) ? (unsigned)g_cnt[idx] : 0u;
        loc[i] = c; s += c;
    }
    unsigned sc = s;
    #pragma unroll
    for (int off = 1; off < 32; off <<= 1) {
        unsigned v = __shfl_up_sync(0xffffffffu, sc, off);
        if (lane >= off) sc += v;
    }
    if (lane == 31) wsum[wid] = sc;
    __syncthreads();
    if (wid == 0) {
        unsigned v = wsum[lane];
        #pragma unroll
        for (int off = 1; off < 32; off <<= 1) {
            unsigned u2 = __shfl_up_sync(0xffffffffu, v, off);
            if (lane >= off) v += u2;
        }
        wsum[lane] = v;
    }
    __syncthreads();
    unsigned run = sc - s + (wid ? wsum[wid - 1] : 0u);
    #pragma unroll
    for (int i = 0; i < 10; i++) {
        int idx = t * 10 + i;
        if (idx < NN) {
            g_ptr[idx] = (int)run; g_cur[idx] = (int)run; run += loc[i];
            g_cnt[idx] = 0;
        }
    }
    if (t == 1023) g_ptr[NN] = (int)wsum[31];
    if (t == 0) {
        float p = 0.0f;
        for (int w = 0; w < 40; w++) p += g_partial[w];
        g_pna = p / (float)NN;
    }
}

__global__ void k_scatter(const int* __restrict__ ei, const int* __restrict__ ea) {
    int e = blockIdx.x * blockDim.x + threadIdx.x;
    if (e >= EDOUB) return;
    int src = ei[e];
    int dst = ei[(e + EORIG) % EDOUB];
    int a   = ea[e % EORIG];
    int pos = atomicAdd(&g_cur[dst], 1);
    g_adj[pos] = src | (a << 16);
}

// ------------------------- fused prep -------------------------
// blocks [0,256): baseB(deg=blk); 256: headscore; 257: dirty; 258: qpart
__global__ void k_prep(const int* __restrict__ h_index,
                       const int* __restrict__ r_index,
                       const float* __restrict__ hstates,
                       const float* __restrict__ relT,
                       const float* __restrict__ Wlin,
                       const float* __restrict__ blin,
                       const float* __restrict__ W1,
                       const float* __restrict__ b1,
                       const float* __restrict__ W2,
                       const float* __restrict__ b2,
                       const float* __restrict__ convb) {   // 128 threads
    int blk = blockIdx.x, t = threadIdx.x;
    if (blk < 256) {
        __shared__ float sqp[64], supd[64], sx[64], sred[64];
        int deg = blk;
        int r0 = r_index[0];
        if (t < 64) {
            float acc = blin[t];
            for (int d = 0; d < DD; d++)
                acc += relT[r0 * DD + d] * Wlin[(DD + d) * DD + t];
            sqp[t] = acc;
        }
        float pna = g_pna;
        float sl = logf((float)deg + 1.0f);
        float amp = sl / pna;
        float att = pna / (sl + 1e-6f);
        if (t < 64) {
            float u = g_csum[t] + amp * g_csum[64 + t] + att * g_csum[128 + t] + convb[t];
            supd[t] = fmaxf(u, 0.0f);
        }
        __syncthreads();
        if (t < 64) {
            float heur = sqp[t];
            for (int d = 0; d < 64; d++) heur += supd[d] * Wlin[d * DD + t];
            sx[t] = supd[t] * heur;
        }
        __syncthreads();
        if (t < 64) {
            float p = 0.0f;
            #pragma unroll
            for (int oo = 0; oo < 2; oo++) {
                int o = t * 2 + oo;
                float a = b1[o];
                for (int d = 0; d < 64; d++) a += sx[d] * W1[d * 128 + o];
                p += fmaxf(a, 0.0f) * W2[o];
            }
            sred[t] = p;
        }
        __syncthreads();
        for (int off = 32; off > 0; off >>= 1) {
            if (t < off) sred[t] += sred[t + off];
            __syncthreads();
        }
        if (t < 64) g_updB[deg * 64 + t] = supd[t];
        if (t == 0) g_scoreB[deg] = sred[0] + b2[0];
    } else if (blk == 256) {
        __shared__ float sx2[4][64];
        int b = t >> 5, ln = t & 31;
        int r0 = r_index[b * 16];
        const float* hv = hstates + b * DD;
        const float* rv = relT + r0 * DD;
        #pragma unroll
        for (int half = 0; half < 2; half++) {
            int c = ln + half * 32;
            float acc = blin[c];
            for (int d = 0; d < DD; d++)
                acc += hv[d] * Wlin[d * DD + c] + rv[d] * Wlin[(DD + d) * DD + c];
            sx2[b][c] = hv[c] * acc;
        }
        __syncwarp();
        float sp = 0.0f;
        #pragma unroll
        for (int oo = 0; oo < 4; oo++) {
            int o = ln * 4 + oo;
            float a2 = b1[o];
            for (int d = 0; d < DD; d++) a2 += sx2[b][d] * W1[d * 128 + o];
            a2 = fmaxf(a2, 0.0f);
            sp += a2 * W2[o];
        }
        #pragma unroll
        for (int off = 16; off > 0; off >>= 1)
            sp += __shfl_down_sync(0xffffffffu, sp, off);
        if (ln == 0) g_headsc[b] = sp + b2[0];
    } else if (blk == 257) {
        int wb = t >> 5, ln = t & 31;
        int h = h_index[wb * 16];
        int p0 = g_ptr[h], p1 = g_ptr[h + 1];
        if (ln == 0) {
            int v = wb * NN + h;
            if (atomicExch(&g_dirty[v], 1) == 0) { int pos = atomicAdd(&g_nd, 1); g_dlist[pos] = v; }
        }
        for (int p = p0 + ln; p < p1; p += 32) {
            int u = g_adj[p] & 0xFFFF;
            int v = wb * NN + u;
            if (atomicExch(&g_dirty[v], 1) == 0) { int pos = atomicAdd(&g_nd, 1); g_dlist[pos] = v; }
        }
        __syncthreads();
        if (t == 0) g_wl = NN + g_nd;
    } else {
        if (t < DD) {
            int r0 = r_index[0];
            float acc = blin[t];
            for (int d = 0; d < DD; d++)
                acc += relT[r0 * DD + d] * Wlin[(DD + d) * DD + t];
            g_qpart[t] = acc;
        }
    }
}

// ------------------------- aggregation (float2 lanes) -------------------------
__device__ __forceinline__ void writeFeat2(int row, int lane, int deg,
                                           float s0, float s1, float q0, float q1,
                                           float mx0, float mx1, float mn0, float mn1) {
    int d = lane * 2;
    float fdeg = (float)deg;
    float den = fmaxf(fdeg, 1.0f);
    float me0 = s0 / den, me1 = s1 / den;
    float sd0 = sqrtf(fmaxf(q0 / den - me0 * me0, 0.0f) + 1e-6f);
    float sd1 = sqrtf(fmaxf(q1 / den - me1 * me1, 0.0f) + 1e-6f);
    if (deg == 0) { mx0 = 0; mx1 = 0; mn0 = 0; mn1 = 0; }
    float* F = g_feat + (size_t)row * 256;
    *(float2*)(F + d)       = make_float2(me0, me1);
    *(float2*)(F + 64 + d)  = make_float2(mx0, mx1);
    *(float2*)(F + 128 + d) = make_float2(mn0, mn1);
    *(float2*)(F + 192 + d) = make_float2(sd0, sd1);
    if (lane == 0) g_deg[row] = fdeg;
}

// blocks [0,1250): copy-0 base agg; [1250,1314): dirty agg (analytic layer-0 state)
__global__ void k_agg0(const float* __restrict__ text, const float* __restrict__ relw,
                       const int* __restrict__ h_index, const float* __restrict__ hstates) {
    int blk = blockIdx.x;
    int lane = threadIdx.x & 31;
    int d = lane * 2;
    const float* rw = relw;   // l = 0
    if (blk < 1250) {
        int v = blk * 8 + (threadIdx.x >> 5);
        if (v >= NN) return;
        int p0 = g_ptr[v], p1 = g_ptr[v + 1];
        float s0 = 0, s1 = 0, q0 = 0, q1 = 0;
        float mx0 = -INFINITY, mx1 = -INFINITY, mn0 = INFINITY, mn1 = INFINITY;
        int deg = 0;
        for (int p = p0; p < p1; p++) {
            int pk = __ldg(&g_adj[p]);
            int u = pk & 0xFFFF, a = pk >> 16;
            float2 tv = *(const float2*)(text + (size_t)u * DD + d);
            float2 rv = *(const float2*)(rw + a * DD + d);
            float m0 = 0.5f * tv.x * rv.x;
            float m1 = 0.5f * tv.y * rv.y;
            s0 += m0; q0 += m0 * m0; mx0 = fmaxf(mx0, m0); mn0 = fminf(mn0, m0);
            s1 += m1; q1 += m1 * m1; mx1 = fmaxf(mx1, m1); mn1 = fminf(mn1, m1);
            deg++;
        }
        writeFeat2(v, lane, deg, s0, s1, q0, q1, mx0, mx1, mn0, mn1);
    } else {
        int j = (blk - 1250) * 8 + (threadIdx.x >> 5);
        if (j >= g_nd) return;
        int v = g_dlist[j];
        int b = v / NN;
        int lv = v - b * NN;
        int hb = h_index[b * 16];
        float hsb = g_headsc[b];
        const float* hrow = hstates + b * DD;
        int p0 = g_ptr[lv], p1 = g_ptr[lv + 1];
        float s0 = 0, s1 = 0, q0 = 0, q1 = 0;
        float mx0 = -INFINITY, mx1 = -INFINITY, mn0 = INFINITY, mn1 = INFINITY;
        int deg = 0;
        for (int p = p0; p < p1; p++) {
            int pk = __ldg(&g_adj[p]);
            int u = pk & 0xFFFF, a = pk >> 16;
            bool ishead = (u == hb);
            float scu = ishead ? hsb : 0.0f;
            if (scu >= 0.0f) {
                float wgt = 1.0f / (1.0f + __expf(-scu));
                float h0v, h1v;
                if (ishead) { h0v = hrow[d]; h1v = hrow[d + 1]; }
                else if (b == 0) {
                    float2 tv = *(const float2*)(text + (size_t)u * DD + d);
                    h0v = tv.x; h1v = tv.y;
                } else { h0v = 0.0f; h1v = 0.0f; }
                float2 rv = *(const float2*)(rw + a * DD + d);
                float m0 = wgt * h0v * rv.x;
                float m1 = wgt * h1v * rv.y;
                s0 += m0; q0 += m0 * m0; mx0 = fmaxf(mx0, m0); mn0 = fminf(mn0, m0);
                s1 += m1; q1 += m1 * m1; mx1 = fmaxf(mx1, m1); mn1 = fminf(mn1, m1);
                deg++;
            }
        }
        writeFeat2(NN + j, lane, deg, s0, s1, q0, q1, mx0, mx1, mn0, mn1);
    }
}

// ---------- dual-threshold 3-pass radix select, single persistent kernel ---
__global__ void k_sel3() {
    int t = threadIdx.x;
    __shared__ int lastf;
    __shared__ unsigned ss[256];
    __shared__ unsigned rBin, rKrem;
    __shared__ float sThr, sTw;
    __shared__ unsigned relbase;
    if (t == 0) relbase = *((volatile unsigned*)&g_release);
    __syncthreads();

    for (int pass = 0; pass < 3; pass++) {
        const int shift = (pass == 0) ? 21 : (pass == 1) ? 10 : 0;
        const unsigned nb = (pass == 2) ? 1024u : 2048u;
        unsigned prefC = 0, prefW = 0;
        if (pass > 0) { prefC = g_prefixC; prefW = g_prefixW; }
        int i = blockIdx.x * 256 + t;
        unsigned binC = 0xFFFFFFFFu, binW = 0xFFFFFFFFu, w = 0;
        if (i < NT) {
            unsigned key = f2key(g_score[i]);
            int lv = i - (i / NN) * NN;
            w = (unsigned)(g_ptr[lv + 1] - g_ptr[lv]);
            bool mC, mW;
            if (pass == 0) { mC = true; mW = true; }
            else if (pass == 1) { mC = ((key >> 21) == (prefC >> 21)); mW = ((key >> 21) == (prefW >> 21)); }
            else { mC = ((key >> 10) == (prefC >> 10)); mW = ((key >> 10) == (prefW >> 10)); }
            unsigned bb = (key >> shift) & (nb - 1u);
            if (mC) binC = bb;
            if (mW) binW = bb;
        }
        warpHistAdd(g_binsA, binC, 1, nb);
        warpHistAdd(g_binsB, binW, w, nb);
        __threadfence();
        if (t == 0) lastf = (atomicAdd(&g_ticket, 1) == SELB * (pass + 1) - 1);
        __syncthreads();

        if (lastf) {
            const int chunk = (int)(nb >> 8);
            {
                unsigned loc[8]; unsigned s = 0;
                #pragma unroll
                for (int j = 0; j < 8; j++) { loc[j] = (j < chunk) ? g_binsA[t * chunk + j] : 0u; s += loc[j]; }
                ss[t] = s;
                __syncthreads();
                for (int off = 1; off < 256; off <<= 1) {
                    unsigned v = (t + off < 256) ? ss[t + off] : 0u;
                    __syncthreads();
                    ss[t] += v;
                    __syncthreads();
                }
                unsigned kk = (pass == 0) ? KS_N : g_kremC;
                unsigned cumTop = (t < 255) ? ss[t + 1] : 0u;
                if (cumTop < kk && cumTop + s >= kk) {
                    unsigned c = cumTop;
                    for (int j = chunk - 1; j >= 0; j--) {
                        if (c + loc[j] >= kk) { rBin = (unsigned)(t * chunk + j); rKrem = kk - c; break; }
                        c += loc[j];
                    }
                }
                __syncthreads();
                if (t == 0) {
                    unsigned npref = prefC | (rBin << shift);
                    if (pass < 2) { g_prefixC = npref; g_kremC = rKrem; }
                    else sThr = key2f(npref);
                }
                __syncthreads();
            }
            {
                unsigned loc[8]; unsigned s = 0;
                #pragma unroll
                for (int j = 0; j < 8; j++) { loc[j] = (j < chunk) ? g_binsB[t * chunk + j] : 0u; s += loc[j]; }
                ss[t] = s;
                __syncthreads();
                for (int off = 1; off < 256; off <<= 1) {
                    unsigned v = (t + off < 256) ? ss[t + off] : 0u;
                    __syncthreads();
                    ss[t] += v;
                    __syncthreads();
                }
                unsigned kk = (pass == 0) ? ES_E : g_kremW;
                unsigned cumTop = (t < 255) ? ss[t + 1] : 0u;
                if (cumTop < kk && cumTop + s >= kk) {
                    unsigned c = cumTop;
                    for (int j = chunk - 1; j >= 0; j--) {
                        if (c + loc[j] >= kk) { rBin = (unsigned)(t * chunk + j); rKrem = kk - c; break; }
                        c += loc[j];
                    }
                }
                __syncthreads();
                if (t == 0) {
                    unsigned npref = prefW | (rBin << shift);
                    if (pass < 2) { g_prefixW = npref; g_kremW = rKrem; }
                    else sTw = key2f(npref);
                }
                __syncthreads();
            }
            #pragma unroll
            for (int j = 0; j < 8; j++)
                if (j < chunk) { g_binsA[t * chunk + j] = 0; g_binsB[t * chunk + j] = 0; }
            __syncthreads();
            if (t == 0) {
                if (pass == 2) {
                    g_thr = sThr; g_T = fmaxf(sThr, sTw); g_wl = 0;
                    g_ticket = 0;
                }
                __threadfence();
                atomicExch(&g_release, relbase + (unsigned)(pass + 1));
            }
            __syncthreads();
        } else {
            if (t == 0) {
                while (*((volatile unsigned*)&g_release) < relbase + (unsigned)(pass + 1))
                    __nanosleep(64);
            }
            __syncthreads();
            __threadfence();
        }
    }
}

// Layers 1-2: fused worklist + exact agg (float2).
__global__ void k_aggSel(const float* __restrict__ relw, int l) {
    int i = blockIdx.x * 8 + (threadIdx.x >> 5);   // grid 5000
    if (i >= NT) return;
    int lane = threadIdx.x & 31;
    int base = (i / NN) * NN;
    int lv = i - base;
    int p0 = g_ptr[lv], p1 = g_ptr[lv + 1];
    float T = g_T;
    if (p1 == p0 || !(g_score[i] >= T)) return;
    int row = 0;
    if (lane == 0) row = atomicAdd(&g_wl, 1);
    row = __shfl_sync(0xffffffffu, row, 0);
    int d = lane * 2;
    const float* rw = relw + l * 400 * DD;
    float s0 = 0, s1 = 0, q0 = 0, q1 = 0;
    float mx0 = -INFINITY, mx1 = -INFINITY, mn0 = INFINITY, mn1 = INFINITY;
    int deg = 0;
    for (int p = p0; p < p1; p++) {
        int pk = __ldg(&g_adj[p]);
        int u = pk & 0xFFFF, a = pk >> 16;
        int gu = base + u;
        float sc = g_score[gu];
        if (sc >= T) {
            float wgt = 1.0f / (1.0f + __expf(-sc));
            float2 hv = *(const float2*)(g_hidden + (size_t)gu * DD + d);
            float2 rv = *(const float2*)(rw + a * DD + d);
            float m0 = wgt * hv.x * rv.x;
            float m1 = wgt * hv.y * rv.y;
            s0 += m0; q0 += m0 * m0; mx0 = fmaxf(mx0, m0); mn0 = fminf(mn0, m0);
            s1 += m1; q1 += m1 * m1; mx1 = fmaxf(mx1, m1); mn1 = fminf(mn1, m1);
            deg++;
        }
    }
    writeFeat2(row, lane, deg, s0, s1, q0, q1, mx0, mx1, mn0, mn1);
    if (lane == 0) g_wlist[row] = i;
}

// Layer-0 GEMM: C[cnt,192] = feat[cnt,256] @ Wcat[256,192]; 128x64 tile, 8x4 micro
__global__ void k_gemm(int l) {
    __shared__ float sA[16 * 128];
    __shared__ float sB[16 * 64];
    int cnt = g_wl;
    int rowBase = blockIdx.x * 128;
    if (rowBase >= cnt) return;
    int colBase = blockIdx.y * 64;
    int t = threadIdx.x;
    int tx = t & 15, ty = t >> 4;
    const float* Wb = g_Wcat + l * 256 * 192;
    float acc[8][4] = {};
    for (int k0 = 0; k0 < 256; k0 += 16) {
        #pragma unroll
        for (int q = 0; q < 2; q++) {
            int lin = t * 2 + q;
            int r = lin >> 2, kq = lin & 3;
            float4 av = make_float4(0, 0, 0, 0);
            int row = rowBase + r;
            if (row < cnt) av = *(const float4*)(g_feat + (size_t)row * 256 + k0 + kq * 4);
            sA[(kq * 4 + 0) * 128 + r] = av.x;
            sA[(kq * 4 + 1) * 128 + r] = av.y;
            sA[(kq * 4 + 2) * 128 + r] = av.z;
            sA[(kq * 4 + 3) * 128 + r] = av.w;
        }
        {
            int kb = t >> 4, j4 = (t & 15) * 4;
            float4 bv = *(const float4*)(Wb + (size_t)(k0 + kb) * 192 + colBase + j4);
            *(float4*)&sB[kb * 64 + j4] = bv;
        }
        __syncthreads();
        #pragma unroll
        for (int kk = 0; kk < 16; kk++) {
            float4 a0 = *(float4*)&sA[kk * 128 + ty * 8];
            float4 a1 = *(float4*)&sA[kk * 128 + ty * 8 + 4];
            float4 b0 = *(float4*)&sB[kk * 64 + tx * 4];
            float a[8] = {a0.x, a0.y, a0.z, a0.w, a1.x, a1.y, a1.z, a1.w};
            float bb[4] = {b0.x, b0.y, b0.z, b0.w};
            #pragma unroll
            for (int i = 0; i < 8; i++)
                #pragma unroll
                for (int j = 0; j < 4; j++)
                    acc[i][j] += a[i] * bb[j];
        }
        __syncthreads();
    }
    #pragma unroll
    for (int i = 0; i < 8; i++) {
        int row = rowBase + ty * 8 + i;
        if (row < cnt) {
            float4 v = make_float4(acc[i][0], acc[i][1], acc[i][2], acc[i][3]);
            *(float4*)(g_C + (size_t)row * 192 + colBase + tx * 4) = v;
        }
    }
}

// Layers 1-2 fused GEMM + post. 64 rows/block, grid 128.
__global__ void k_gp(const float* __restrict__ convb,
                     const float* __restrict__ Wlin,
                     const float* __restrict__ W1,
                     const float* __restrict__ b1,
                     const float* __restrict__ W2,
                     const float* __restrict__ b2, int l) {
    extern __shared__ float smem[];
    float* sC   = smem;                   // 64*192
    float* sh   = sC + 64 * 192;          // 64*65
    float* sbuf = sh + 64 * 65;           // 64*128
    float* sqp  = sbuf + 64 * 128;
    float* samp = sqp + 64;
    float* satt = samp + 64;
    float* sw2  = satt + 64;
    float* sb1  = sw2 + 128;
    int*   sv   = (int*)(sb1 + 128);      // 64
    float* sA   = (float*)(sv + 64);      // 16*64
    float* sB   = sA + 16 * 64;           // 16*192

    int cnt = g_wl;
    int rowBase = blockIdx.x * 64;
    if (rowBase >= cnt) return;
    int t = threadIdx.x;
    int tx = t & 15, ty = t >> 4;

    if (t < 64) {
        int i = rowBase + t;
        float dg = (i < cnt) ? g_deg[i] : 0.0f;
        float sl = logf(dg + 1.0f);
        float pna = g_pna;
        samp[t] = sl / pna;
        satt[t] = pna / (sl + 1e-6f);
        sv[t] = (i < cnt) ? g_wlist[i] : -1;
        sqp[t] = g_qpart[t];
    }
    if (t < 128) { sw2[t] = W2[t]; sb1[t] = b1[t]; }

    const float* Wb = g_Wcat + l * 256 * 192;
    float acc[4][12] = {};
    for (int k0 = 0; k0 < 256; k0 += 16) {
        {
            int r = t >> 2, kq = t & 3;
            int row = rowBase + r;
            float4 av = make_float4(0, 0, 0, 0);
            if (row < cnt) av = *(const float4*)(g_feat + (size_t)row * 256 + k0 + kq * 4);
            sA[(kq * 4 + 0) * 64 + r] = av.x;
            sA[(kq * 4 + 1) * 64 + r] = av.y;
            sA[(kq * 4 + 2) * 64 + r] = av.z;
            sA[(kq * 4 + 3) * 64 + r] = av.w;
        }
        #pragma unroll
        for (int q = 0; q < 3; q++) {
            int lin = q * 256 + t;
            int kb = lin / 48, c4 = (lin % 48) * 4;
            float4 bv = *(const float4*)(Wb + (size_t)(k0 + kb) * 192 + c4);
            *(float4*)&sB[kb * 192 + c4] = bv;
        }
        __syncthreads();
        #pragma unroll
        for (int kk = 0; kk < 16; kk++) {
            float a[4];
            #pragma unroll
            for (int i = 0; i < 4; i++) a[i] = sA[kk * 64 + ty * 4 + i];
            float b[12];
            #pragma unroll
            for (int q = 0; q < 3; q++) {
                float4 b4 = *(float4*)&sB[kk * 192 + tx * 12 + q * 4];
                b[q * 4 + 0] = b4.x; b[q * 4 + 1] = b4.y;
                b[q * 4 + 2] = b4.z; b[q * 4 + 3] = b4.w;
            }
            #pragma unroll
            for (int i = 0; i < 4; i++)
                #pragma unroll
                for (int j = 0; j < 12; j++)
                    acc[i][j] += a[i] * b[j];
        }
        __syncthreads();
    }
    #pragma unroll
    for (int i = 0; i < 4; i++)
        #pragma unroll
        for (int j = 0; j < 12; j++)
            sC[(ty * 4 + i) * 192 + tx * 12 + j] = acc[i][j];
    __syncthreads();

    #pragma unroll
    for (int q = 0; q < 16; q++) {
        int lin = t + q * 256;
        int r = lin >> 6, dd = lin & 63;
        int i = rowBase + r;
        float nh = 0.0f;
        if (i < cnt) {
            const float* C = sC + r * 192;
            float u = C[dd] + samp[r] * C[64 + dd] + satt[r] * C[128 + dd] + convb[l * 64 + dd];
            u = fmaxf(u, 0.0f);
            int v = sv[r];
            nh = g_hidden[(size_t)v * DD + dd] + u;
            g_hidden[(size_t)v * DD + dd] = nh;
        }
        sh[r * 65 + dd] = nh;
    }
    #pragma unroll
    for (int q = 0; q < 16; q++) {
        int lin = t + q * 256;
        int r = lin >> 6, c = lin & 63;
        sbuf[r * 68 + c] = Wlin[r * DD + c];
    }
    __syncthreads();

    {
        float acc2[4][4] = {};
        for (int k = 0; k < 64; k++) {
            float a[4], bb[4];
            #pragma unroll
            for (int i = 0; i < 4; i++) a[i] = sh[(ty * 4 + i) * 65 + k];
            float4 b4 = *(float4*)&sbuf[k * 68 + tx * 4];
            bb[0] = b4.x; bb[1] = b4.y; bb[2] = b4.z; bb[3] = b4.w;
            #pragma unroll
            for (int i = 0; i < 4; i++)
                #pragma unroll
                for (int j = 0; j < 4; j++)
                    acc2[i][j] += a[i] * bb[j];
        }
        __syncthreads();
        #pragma unroll
        for (int i = 0; i < 4; i++)
            #pragma unroll
            for (int j = 0; j < 4; j++) {
                int r = ty * 4 + i, c = tx * 4 + j;
                float hv = sh[r * 65 + c];
                sh[r * 65 + c] = hv * (acc2[i][j] + sqp[c]);
            }
        __syncthreads();
    }

    #pragma unroll
    for (int q = 0; q < 32; q++) {
        int lin = t + q * 256;
        sbuf[lin] = W1[lin];
    }
    __syncthreads();

    {
        float acc3[4][8] = {};
        for (int k = 0; k < 64; k++) {
            float a[4];
            #pragma unroll
            for (int i = 0; i < 4; i++) a[i] = sh[(ty * 4 + i) * 65 + k];
            float4 b0 = *(float4*)&sbuf[k * 128 + tx * 8];
            float4 b1v = *(float4*)&sbuf[k * 128 + tx * 8 + 4];
            float bb[8] = {b0.x, b0.y, b0.z, b0.w, b1v.x, b1v.y, b1v.z, b1v.w};
            #pragma unroll
            for (int i = 0; i < 4; i++)
                #pragma unroll
                for (int j = 0; j < 8; j++)
                    acc3[i][j] += a[i] * bb[j];
        }
        float bias2 = b2[0];
        #pragma unroll
        for (int i = 0; i < 4; i++) {
            float p = 0.0f;
            #pragma unroll
            for (int j = 0; j < 8; j++) {
                int o = tx * 8 + j;
                p += fmaxf(acc3[i][j] + sb1[o], 0.0f) * sw2[o];
            }
            p += __shfl_xor_sync(0xffffffffu, p, 1);
            p += __shfl_xor_sync(0xffffffffu, p, 2);
            p += __shfl_xor_sync(0xffffffffu, p, 4);
            p += __shfl_xor_sync(0xffffffffu, p, 8);
            if ((t & 15) == 0) {
                int i2 = rowBase + ty * 4 + i;
                if (i2 < cnt) {
                    int v = sv[ty * 4 + i];
                    g_score[v] = p + bias2;
                }
            }
        }
    }
}

// Layer-0 post + broadcast. blocks [0,165) post0 (reads g_C); [165,2040) bcast.
__global__ void k_post0x(const float* __restrict__ text,
                         const float* __restrict__ convb,
                         const float* __restrict__ Wlin,
                         const float* __restrict__ W1,
                         const float* __restrict__ b1,
                         const float* __restrict__ W2,
                         const float* __restrict__ b2,
                         const int* __restrict__ h_index,
                         const float* __restrict__ hstates) {
    int t = threadIdx.x;
    if (blockIdx.x >= 165) {
        int idx = (blockIdx.x - 165) * 256 + t;
        if (idx >= 3 * NN * 16) return;
        int v = NN + (idx >> 4), q = idx & 15;
        if (g_dirty[v]) return;
        int lv = v - (v / NN) * NN;
        int deg = g_ptr[lv + 1] - g_ptr[lv];
        float4 uv = make_float4(0, 0, 0, 0);
        float scv = 0.0f;
        if (deg > 0) {
            int dc = min(deg, 255);
            uv = *(const float4*)(g_updB + dc * 64 + q * 4);
            scv = g_scoreB[dc];
        }
        *(float4*)(g_hidden + (size_t)v * DD + q * 4) = uv;
        if (q == 0) g_score[v] = scv;
        return;
    }
    extern __shared__ float smem[];
    float* sh   = smem;
    float* sbuf = smem + 64 * 65;
    float* sqp  = sbuf + 64 * 128;
    float* samp = sqp + 64;
    float* satt = samp + 64;
    float* sw2  = satt + 64;
    float* sb1  = sw2 + 128;
    float* ss0  = sb1 + 128;
    int*   svg  = (int*)(ss0 + 64);
    int*   som  = svg + 64;

    int cnt = g_wl;
    int rowBase = blockIdx.x * 64;
    if (rowBase >= cnt) return;

    if (t < 64) {
        int i = rowBase + t;
        float dg = 0.0f; int vg = 0; int flags = 0; float sc0 = 0.0f;
        if (i < cnt) {
            dg = g_deg[i];
            if (i < NN) {
                vg = i;
                flags = 2 | ((g_ptr[i + 1] > g_ptr[i]) ? 1 : 0) | (g_dirty[i] ? 4 : 0);
            } else {
                int v = g_dlist[i - NN]; vg = v;
                int b = v / NN;
                int lv = v - b * NN;
                int sdeg = g_ptr[lv + 1] - g_ptr[lv];
                int hb = h_index[b * 16];
                bool ishead = (lv == hb);
                float hs = ishead ? g_headsc[b] : 0.0f;
                sc0 = hs;
                flags = ((hs >= 0.0f) && sdeg > 0) ? 1 : 0;
                if (ishead) flags |= 8;
            }
        }
        float sl = logf(dg + 1.0f);
        float pna = g_pna;
        samp[t] = sl / pna;
        satt[t] = pna / (sl + 1e-6f);
        svg[t] = vg; som[t] = flags; ss0[t] = sc0;
        sqp[t] = g_qpart[t];
    }
    if (t < 128) { sw2[t] = W2[t]; sb1[t] = b1[t]; }
    __syncthreads();

    #pragma unroll
    for (int q = 0; q < 16; q++) {
        int lin = t + q * 256;
        int r = lin >> 6, dd = lin & 63;
        int i = rowBase + r;
        float nh = 0.0f;
        if (i < cnt) {
            int flags = som[r]; int vg = svg[r];
            float pre;
            if (flags & 2) pre = text[(size_t)vg * DD + dd];
            else {
                int b = vg / NN; int lv = vg - b * NN;
                if (flags & 8) pre = hstates[b * DD + dd];
                else pre = (b == 0) ? text[(size_t)lv * DD + dd] : 0.0f;
            }
            float u = 0.0f;
            if (flags & 1) {
                const float* C = g_C + (size_t)i * 192;
                u = fmaxf(C[dd] + samp[r] * C[64 + dd] + satt[r] * C[128 + dd] + convb[dd], 0.0f);
            }
            nh = pre + u;
            if (flags & 2) {
                if (!(flags & 4)) g_hidden[(size_t)vg * DD + dd] = nh;
            } else {
                g_hidden[(size_t)vg * DD + dd] = nh;
            }
        }
        sh[r * 65 + dd] = nh;
    }
    #pragma unroll
    for (int q = 0; q < 16; q++) {
        int lin = t + q * 256;
        int r = lin >> 6, c = lin & 63;
        sbuf[r * 68 + c] = Wlin[r * DD + c];
    }
    __syncthreads();

    int tx = t & 15, ty = t >> 4;
    {
        float acc[4][4] = {};
        for (int k = 0; k < 64; k++) {
            float a[4], bb[4];
            #pragma unroll
            for (int i = 0; i < 4; i++) a[i] = sh[(ty * 4 + i) * 65 + k];
            float4 b4 = *(float4*)&sbuf[k * 68 + tx * 4];
            bb[0] = b4.x; bb[1] = b4.y; bb[2] = b4.z; bb[3] = b4.w;
            #pragma unroll
            for (int i = 0; i < 4; i++)
                #pragma unroll
                for (int j = 0; j < 4; j++)
                    acc[i][j] += a[i] * bb[j];
        }
        __syncthreads();
        #pragma unroll
        for (int i = 0; i < 4; i++)
            #pragma unroll
            for (int j = 0; j < 4; j++) {
                int r = ty * 4 + i, c = tx * 4 + j;
                float hv = sh[r * 65 + c];
                sh[r * 65 + c] = hv * (acc[i][j] + sqp[c]);
            }
        __syncthreads();
    }

    #pragma unroll
    for (int q = 0; q < 32; q++) {
        int lin = t + q * 256;
        sbuf[lin] = W1[lin];
    }
    __syncthreads();

    {
        float acc[4][8] = {};
        for (int k = 0; k < 64; k++) {
            float a[4];
            #pragma unroll
            for (int i = 0; i < 4; i++) a[i] = sh[(ty * 4 + i) * 65 + k];
            float4 b0 = *(float4*)&sbuf[k * 128 + tx * 8];
            float4 b1v = *(float4*)&sbuf[k * 128 + tx * 8 + 4];
            float bb[8] = {b0.x, b0.y, b0.z, b0.w, b1v.x, b1v.y, b1v.z, b1v.w};
            #pragma unroll
            for (int i = 0; i < 4; i++)
                #pragma unroll
                for (int j = 0; j < 8; j++)
                    acc[i][j] += a[i] * bb[j];
        }
        float bias2 = b2[0];
        #pragma unroll
        for (int i = 0; i < 4; i++) {
            float p = 0.0f;
            #pragma unroll
            for (int j = 0; j < 8; j++) {
                int o = tx * 8 + j;
                p += fmaxf(acc[i][j] + sb1[o], 0.0f) * sw2[o];
            }
            p += __shfl_xor_sync(0xffffffffu, p, 1);
            p += __shfl_xor_sync(0xffffffffu, p, 2);
            p += __shfl_xor_sync(0xffffffffu, p, 4);
            p += __shfl_xor_sync(0xffffffffu, p, 8);
            if ((t & 15) == 0) {
                int i2 = rowBase + ty * 4 + i;
                if (i2 < cnt) {
                    int rr = ty * 4 + i;
                    int flags = som[rr];
                    int vg = svg[rr];
                    float sc = p + bias2;
                    if (flags & 2) {
                        if (!(flags & 4)) g_score[vg] = (flags & 1) ? sc : 0.0f;
                    } else {
                        g_score[vg] = (flags & 1) ? sc : ss0[rr];
                    }
                }
            }
        }
    }
}

__global__ void k_out(const int* __restrict__ t_index, float* __restrict__ out) {
    int t = threadIdx.x;
    if (t >= 64) return;
    int b = t / 16;
    int v = t_index[t] + b * NN;
    out[t] = g_score[v];
}

// ------------------------- launch -------------------------
extern "C" void kernel_launch(void* const* d_in, const int* in_sizes, int n_in,
                              void* d_out, int out_size) {
    const int*   h_index   = (const int*)d_in[0];
    const int*   r_index   = (const int*)d_in[1];
    const int*   t_index   = (const int*)d_in[2];
    const float* hstates   = (const float*)d_in[3];
    const int*   edge_idx  = (const int*)d_in[5];
    const int*   edge_attr = (const int*)d_in[6];
    const float* text      = (const float*)d_in[7];
    const float* relT      = (const float*)d_in[9];
    const float* Wlin      = (const float*)d_in[10];
    const float* blin      = (const float*)d_in[11];
    const float* W1        = (const float*)d_in[12];
    const float* b1        = (const float*)d_in[13];
    const float* W2        = (const float*)d_in[14];
    const float* b2        = (const float*)d_in[15];
    const float* relw      = (const float*)d_in[16];
    const float* convW     = (const float*)d_in[17];
    const float* convb     = (const float*)d_in[18];
    float* out = (float*)d_out;

    const int SMEM_POST0 = (64 * 65 + 64 * 128 + 64 * 3 + 128 * 2 + 64 + 128) * 4;
    const int SMEM_GP    = (64 * 192 + 64 * 65 + 64 * 128 + 64 * 3 + 128 * 2 + 64
                            + 16 * 64 + 16 * 192) * 4;
    static int attr_done = 0;
    if (!attr_done) {
        cudaFuncSetAttribute(k_post0x, cudaFuncAttributeMaxDynamicSharedMemorySize, SMEM_POST0);
        cudaFuncSetAttribute(k_gp, cudaFuncAttributeMaxDynamicSharedMemorySize, SMEM_GP);
        attr_done = 1;
    }

    k_setup<<<1125, 256>>>(convW, edge_idx);
    k_scanA<<<40, 256>>>();
    k_scan<<<1, 1024>>>();
    k_scatter<<<391, 256>>>(edge_idx, edge_attr);
    k_prep<<<259, 128>>>(h_index, r_index, hstates, relT, Wlin, blin, W1, b1, W2, b2, convb);

    // ---- layer 0 (thr = T = 0 statically; analytic init state) ----
    k_agg0<<<1314, 256>>>(text, relw, h_index, hstates);
    k_gemm<<<dim3(83, 3), 256>>>(0);
    k_post0x<<<2040, 256, SMEM_POST0>>>(text, convb, Wlin, W1, b1, W2, b2, h_index, hstates);

    // ---- layers 1-2 ----
    for (int l = 1; l < 3; l++) {
        k_sel3<<<SELB, 256>>>();
        k_aggSel<<<5000, 256>>>(relw, l);
        k_gp<<<128, 256, SMEM_GP>>>(convb, Wlin, W1, b1, W2, b2, l);
    }
    k_out<<<1, 64>>>(t_index, out);
}